// round 16
// baseline (speedup 1.0000x reference)
#include <cuda_runtime.h>
#include <cuda_fp16.h>
#include <math.h>
#include <stdint.h>

#define MAX_NODES 50000
#define MAX_EDGES 1600000
#define HC        128        // HEADS * OUT_DIM
#define HEADS     4
#define IN_DIM    128
#define NEG_SLOPE 0.04821699482733621f
#define BN_EPS    1e-5f

// ---------------- scratch (static __device__ — no allocations allowed) ----------
__device__ __align__(16) __half g_hh[MAX_NODES * HC];   // fp16 message features
__device__ __align__(16) float g_as   [MAX_NODES * HEADS];
__device__ __align__(16) float g_ad   [MAX_NODES * HEADS];
__device__ __align__(16) int g_src [MAX_EDGES];
__device__ __align__(16) int g_dst [MAX_EDGES];
__device__ int   g_esrc [MAX_EDGES];      // CSR: src ids grouped by dst
__device__ int   g_deg  [MAX_NODES];
__device__ int   g_off  [MAX_NODES];
__device__ int   g_fill [MAX_NODES];
__device__ int   g_bsum [256];            // per-block scan sums (<=196 used)
__device__ int   g_boff [256];
__device__ int   g_idx_mode;              // 0=int32, 1=int64, 2=float32
__device__ __align__(16) float g_bnsum  [HC];
__device__ __align__(16) float g_bnsumsq[HC];
__device__ float g_scale  [HC];
__device__ float g_shift  [HC];

// Resolved parameter-vector pointers (runtime input-order detection)
__device__ const float* gp_a_src;
__device__ const float* gp_a_dst;
__device__ const float* gp_bias;
__device__ const float* gp_gamma;
__device__ const float* gp_beta;

// ---------------- helpers ----------------
__device__ __forceinline__ float warp_sum(float v) {
    v += __shfl_xor_sync(0xffffffffu, v, 16);
    v += __shfl_xor_sync(0xffffffffu, v, 8);
    v += __shfl_xor_sync(0xffffffffu, v, 4);
    v += __shfl_xor_sync(0xffffffffu, v, 2);
    v += __shfl_xor_sync(0xffffffffu, v, 1);
    return v;
}

__device__ __forceinline__ int warp_incl_scan(int v) {
    const int lane = threadIdx.x & 31;
    #pragma unroll
    for (int d = 1; d < 32; d <<= 1) {
        int t = __shfl_up_sync(0xffffffffu, v, d);
        if (lane >= d) v += t;
    }
    return v;
}

__device__ __forceinline__ float lrelu(float e) {
    return e >= 0.f ? e : NEG_SLOPE * e;
}

// unpack 4 fp16 channels (8 bytes) to float4
__device__ __forceinline__ float4 h4_to_f4(uint2 u) {
    __half2 a = *reinterpret_cast<__half2*>(&u.x);
    __half2 b = *reinterpret_cast<__half2*>(&u.y);
    return make_float4(__low2float(a), __high2float(a),
                       __low2float(b), __high2float(b));
}

// ---------------- K_detect_vec: resolve the five 128-float parameter vectors ----
__global__ void k_detect_vec(const float* p0, const float* p1, const float* p2,
                             const float* p3, const float* p4)
{
    const int t = threadIdx.x;
    int ones3 = __syncthreads_and(p3[t] == 1.0f);
    int ones4 = __syncthreads_and(p4[t] == 1.0f);
    if (t == 0) {
        if (ones3) {            // insertion order: a_src,a_dst,bias,gamma,beta
            gp_a_src = p0; gp_a_dst = p1; gp_bias = p2; gp_gamma = p3; gp_beta = p4;
        } else if (ones4) {     // alphabetical: a_dst,a_src,beta,bias,gamma
            gp_a_dst = p0; gp_a_src = p1; gp_beta = p2; gp_bias = p3; gp_gamma = p4;
        } else {
            gp_a_src = p0; gp_a_dst = p1; gp_bias = p2; gp_gamma = p3; gp_beta = p4;
        }
    }
}

// ---------------- K_detect_idx: classify edge_index dtype ----------------------
__global__ void k_detect_idx(const unsigned int* __restrict__ w, int n_edges, int n_nodes)
{
    __shared__ int s_hi_nz, s_int_ok, s_flt_ok;
    const int t = threadIdx.x;
    if (t == 0) { s_hi_nz = 0; s_int_ok = 0; s_flt_ok = 0; }
    __syncthreads();

    const int SAMPLES = 1024;
    const long long total_words = 2LL * n_edges;
    int hi_nz = 0, int_ok = 0, flt_ok = 0;
    for (int i = t; i < SAMPLES; i += blockDim.x) {
        long long pair = (long long)i * ((total_words / 2) / SAMPLES);
        unsigned int lo = w[2 * pair];
        unsigned int hi = w[2 * pair + 1];
        if (hi != 0u) hi_nz++;
        int vi = (int)lo;
        if (vi >= 0 && vi < n_nodes) int_ok++;
        float vf = __uint_as_float(lo);
        if (vf >= 0.f && vf < (float)n_nodes && vf == floorf(vf)) flt_ok++;
    }
    atomicAdd(&s_hi_nz, hi_nz);
    atomicAdd(&s_int_ok, int_ok);
    atomicAdd(&s_flt_ok, flt_ok);
    __syncthreads();
    if (t == 0) {
        if (s_hi_nz == 0)               g_idx_mode = 1;
        else if (s_int_ok >= s_flt_ok)  g_idx_mode = 0;
        else                            g_idx_mode = 2;
    }
}

// ---------------- K0: zero degree histogram + BN accumulators -------------------
__global__ void __launch_bounds__(256) k_zero(int n_nodes) {
    int i = blockIdx.x * 256 + threadIdx.x;
    if (i < n_nodes) g_deg[i] = 0;
    if (i < HC) { g_bnsum[i] = 0.f; g_bnsumsq[i] = 0.f; }
}

// ---------------- K_hist: decode indices (clamped) + degree histogram ----------
__global__ void __launch_bounds__(256) k_hist(const void* __restrict__ raw,
                                              int n_edges, int n_nodes)
{
    const int i  = blockIdx.x * 256 + threadIdx.x;   // pair index
    const int e0 = 2 * i;
    if (e0 >= n_edges) return;
    const int  mode = g_idx_mode;
    const bool full = (e0 + 1 < n_edges);

    long long vs0, vs1 = 0, vd0, vd1 = 0;
    if (mode == 1) {
        const longlong2* sp = (const longlong2*)raw;
        const long long* dbase = (const long long*)raw + n_edges;
        longlong2 s = sp[i];
        vs0 = s.x; vs1 = s.y;
        if (((size_t)n_edges & 1) == 0 && full) {
            longlong2 d = ((const longlong2*)dbase)[i];
            vd0 = d.x; vd1 = d.y;
        } else {
            vd0 = dbase[e0];
            vd1 = full ? dbase[e0 + 1] : 0;
        }
    } else if (mode == 0) {
        const int2* sp = (const int2*)raw;
        const int* dbase = (const int*)raw + n_edges;
        int2 s = sp[i];
        vs0 = s.x; vs1 = s.y;
        if (((size_t)n_edges & 1) == 0 && full) {
            int2 d = ((const int2*)dbase)[i];
            vd0 = d.x; vd1 = d.y;
        } else {
            vd0 = dbase[e0];
            vd1 = full ? dbase[e0 + 1] : 0;
        }
    } else {
        const float2* sp = (const float2*)raw;
        const float* dbase = (const float*)raw + n_edges;
        float2 s = sp[i];
        vs0 = (long long)s.x; vs1 = (long long)s.y;
        vd0 = (long long)dbase[e0];
        vd1 = full ? (long long)dbase[e0 + 1] : 0;
    }
    if (vs0 < 0 || vs0 >= n_nodes) vs0 = 0;   // defensive clamp
    if (vs1 < 0 || vs1 >= n_nodes) vs1 = 0;
    if (vd0 < 0 || vd0 >= n_nodes) vd0 = 0;
    if (vd1 < 0 || vd1 >= n_nodes) vd1 = 0;

    if (full) {
        *(int2*)(g_src + e0) = make_int2((int)vs0, (int)vs1);
        *(int2*)(g_dst + e0) = make_int2((int)vd0, (int)vd1);
        atomicAdd(&g_deg[(int)vd0], 1);
        atomicAdd(&g_deg[(int)vd1], 1);
    } else {
        g_src[e0] = (int)vs0;
        g_dst[e0] = (int)vd0;
        atomicAdd(&g_deg[(int)vd0], 1);
    }
}

// ---------------- scan (3 kernels, warp-shuffle based) --------------------------
__global__ void __launch_bounds__(256) k_scan_blk(int n_nodes)
{
    __shared__ int wsum[8];
    const int i    = blockIdx.x * 256 + threadIdx.x;
    const int lane = threadIdx.x & 31;
    const int wid  = threadIdx.x >> 5;

    int v = (i < n_nodes) ? g_deg[i] : 0;
    int s = warp_incl_scan(v);
    if (lane == 31) wsum[wid] = s;
    __syncthreads();
    if (wid == 0) {
        int w  = (lane < 8) ? wsum[lane] : 0;
        int ws = warp_incl_scan(w);
        if (lane < 8) wsum[lane] = ws - w;            // exclusive warp offsets
        if (lane == 7) g_bsum[blockIdx.x] = ws;       // block total
    }
    __syncthreads();
    if (i < n_nodes) g_off[i] = s - v + wsum[wid];
}

__global__ void __launch_bounds__(256) k_scan_top(int nblk)
{
    __shared__ int wsum[8];
    const int t    = threadIdx.x;
    const int lane = t & 31;
    const int wid  = t >> 5;
    int v = (t < nblk) ? g_bsum[t] : 0;
    int s = warp_incl_scan(v);
    if (lane == 31) wsum[wid] = s;
    __syncthreads();
    if (wid == 0) {
        int w  = (lane < 8) ? wsum[lane] : 0;
        int ws = warp_incl_scan(w);
        if (lane < 8) wsum[lane] = ws - w;
    }
    __syncthreads();
    if (t < nblk) g_boff[t] = s - v + wsum[wid];
}

__global__ void __launch_bounds__(256) k_scan_add(int n_nodes)
{
    const int i = blockIdx.x * 256 + threadIdx.x;
    if (i >= n_nodes) return;
    int o = g_off[i] + g_boff[blockIdx.x];
    g_off[i]  = o;
    g_fill[i] = o;
}

// ---------------- K_fill: bucket edge srcs by dst (2 edges/thread) --------------
__global__ void __launch_bounds__(256) k_fill(int n_edges)
{
    const int i  = blockIdx.x * 256 + threadIdx.x;
    const int e0 = 2 * i;
    if (e0 >= n_edges) return;
    if (e0 + 1 < n_edges) {
        int2 s = *(const int2*)(g_src + e0);
        int2 d = *(const int2*)(g_dst + e0);
        int p0 = atomicAdd(&g_fill[d.x], 1);
        int p1 = atomicAdd(&g_fill[d.y], 1);
        g_esrc[p0] = s.x;
        g_esrc[p1] = s.y;
    } else {
        int s = g_src[e0];
        int d = g_dst[e0];
        int p = atomicAdd(&g_fill[d], 1);
        g_esrc[p] = s;
    }
}

// ---------------- K1: h = x @ W (fp32 compute), fp16 store, fp32 alphas ---------
#define GEMM_ROWS 16
#define SX_PAD    20                       // 16 rows padded to 20 (16B-aligned rows)
__global__ void __launch_bounds__(128) k_gemm(
    const float* __restrict__ x, const float* __restrict__ W, int n_nodes)
{
    extern __shared__ float sm[];
    float* sW  = sm;                        // [128][128]
    float* sxT = sm + IN_DIM * HC;          // [128][SX_PAD]  (k-major, rows r)

    const int t    = threadIdx.x;
    const int row0 = blockIdx.x * GEMM_ROWS;

    for (int i = t; i < IN_DIM * HC; i += 128) sW[i] = W[i];
    #pragma unroll
    for (int r = 0; r < GEMM_ROWS; r++) {
        int node = row0 + r;
        sxT[t * SX_PAD + r] = (node < n_nodes) ? x[(size_t)node * IN_DIM + t] : 0.f;
    }
    __syncthreads();

    float acc[GEMM_ROWS];
    #pragma unroll
    for (int r = 0; r < GEMM_ROWS; r++) acc[r] = 0.f;

    #pragma unroll 2
    for (int k = 0; k < IN_DIM; k++) {
        float w = sW[k * HC + t];
        const float4* xr = (const float4*)(sxT + k * SX_PAD);   // broadcast reads
        float4 x0 = xr[0], x1 = xr[1], x2 = xr[2], x3 = xr[3];
        acc[0]  += x0.x * w;  acc[1]  += x0.y * w;  acc[2]  += x0.z * w;  acc[3]  += x0.w * w;
        acc[4]  += x1.x * w;  acc[5]  += x1.y * w;  acc[6]  += x1.z * w;  acc[7]  += x1.w * w;
        acc[8]  += x2.x * w;  acc[9]  += x2.y * w;  acc[10] += x2.z * w;  acc[11] += x2.w * w;
        acc[12] += x3.x * w;  acc[13] += x3.y * w;  acc[14] += x3.z * w;  acc[15] += x3.w * w;
    }

    const float asv  = gp_a_src[t];
    const float adv  = gp_a_dst[t];
    const int   head = t >> 5;
    const int   lane = t & 31;

    #pragma unroll
    for (int r = 0; r < GEMM_ROWS; r++) {
        int node = row0 + r;
        if (node >= n_nodes) break;
        float hv = acc[r];
        g_hh[(size_t)node * HC + t] = __float2half(hv);
        float s = warp_sum(hv * asv);     // fp32 attention logits (exact path)
        float d = warp_sum(hv * adv);
        if (lane == 0) {
            g_as[node * HEADS + head] = s;
            g_ad[node * HEADS + head] = d;
        }
    }
}

// ---------------- K_agg: gather-aggregate + full epilogue -----------------------
// NPW=1 -> 50000 warps (max latency-hiding contexts; zero per-warp imbalance).
// BN partials reduced across the block's 8 warps in smem; one red.v4 pair/block.
#define NPW 1   // nodes per warp
__global__ void __launch_bounds__(256) k_agg(float* __restrict__ out, int n_nodes)
{
    __shared__ float sbn[2][8][HC];          // [sum|sq][warp][channel]

    const int wid  = threadIdx.x >> 5;
    const int warp = blockIdx.x * 8 + wid;
    const int lane = threadIdx.x & 31;
    const int head = lane >> 3;

    const float4 bias4 = *((const float4*)gp_bias + lane);

    float4 lsum = make_float4(0.f, 0.f, 0.f, 0.f);
    float4 lsq  = make_float4(0.f, 0.f, 0.f, 0.f);

    const int node0 = warp * NPW;
    const int node1 = (node0 + NPW < n_nodes) ? node0 + NPW : n_nodes;

    for (int d = node0; d < node1; d++) {
        float adl = 0.f, dsum = 0.f, pself = 0.f;
        if (lane < HEADS) {
            adl   = g_ad[d * HEADS + lane];
            pself = __expf(lrelu(g_as[d * HEADS + lane] + adl));
            dsum  = pself;
        }
        float ps = __shfl_sync(0xffffffffu, pself, head);

        uint2 ud = *((const uint2*)(g_hh + (size_t)d * HC) + lane);
        float4 hd = h4_to_f4(ud);
        float4 acc;
        acc.x = hd.x * ps; acc.y = hd.y * ps; acc.z = hd.z * ps; acc.w = hd.w * ps;

        const int start = g_off[d];
        const int end   = start + g_deg[d];
        int k = start;

        for (; k + 8 <= end; k += 8) {
            int s[8];
            #pragma unroll
            for (int j = 0; j < 8; j++) s[j] = g_esrc[k + j];

            float p[8];
            #pragma unroll
            for (int j = 0; j < 8; j++) p[j] = 0.f;
            if (lane < HEADS) {
                #pragma unroll
                for (int j = 0; j < 8; j++) {
                    p[j] = __expf(lrelu(g_as[s[j] * HEADS + lane] + adl));
                    dsum += p[j];
                }
            }
            uint2 u[8];
            #pragma unroll
            for (int j = 0; j < 8; j++)
                u[j] = *((const uint2*)(g_hh + (size_t)s[j] * HC) + lane);

            #pragma unroll
            for (int j = 0; j < 8; j++) {
                float q = __shfl_sync(0xffffffffu, p[j], head);
                float4 h = h4_to_f4(u[j]);
                acc.x += h.x * q; acc.y += h.y * q; acc.z += h.z * q; acc.w += h.w * q;
            }
        }
        for (; k < end; k++) {
            int s0 = g_esrc[k];
            float p0 = 0.f;
            if (lane < HEADS) {
                p0 = __expf(lrelu(g_as[s0 * HEADS + lane] + adl));
                dsum += p0;
            }
            uint2 u0 = *((const uint2*)(g_hh + (size_t)s0 * HC) + lane);
            float q0 = __shfl_sync(0xffffffffu, p0, head);
            float4 h0 = h4_to_f4(u0);
            acc.x += h0.x * q0; acc.y += h0.y * q0; acc.z += h0.z * q0; acc.w += h0.w * q0;
        }

        float den = __shfl_sync(0xffffffffu, dsum, head);
        float inv = 1.0f / den;

        float4 v;
        v.x = acc.x * inv + bias4.x;
        v.y = acc.y * inv + bias4.y;
        v.z = acc.z * inv + bias4.z;
        v.w = acc.w * inv + bias4.w;

        *((float4*)(out + (size_t)d * HC) + lane) = v;

        lsum.x += v.x; lsum.y += v.y; lsum.z += v.z; lsum.w += v.w;
        lsq.x += v.x * v.x; lsq.y += v.y * v.y; lsq.z += v.z * v.z; lsq.w += v.w * v.w;
    }

    // block-level BN reduction: per-warp partials -> smem -> warp 0 -> one red/block
    *((float4*)&sbn[0][wid][lane * 4]) = lsum;
    *((float4*)&sbn[1][wid][lane * 4]) = lsq;
    __syncthreads();
    if (wid == 0) {
        float4 ts = make_float4(0.f, 0.f, 0.f, 0.f);
        float4 tq = make_float4(0.f, 0.f, 0.f, 0.f);
        #pragma unroll
        for (int w = 0; w < 8; w++) {
            float4 a = *((const float4*)&sbn[0][w][lane * 4]);
            float4 b = *((const float4*)&sbn[1][w][lane * 4]);
            ts.x += a.x; ts.y += a.y; ts.z += a.z; ts.w += a.w;
            tq.x += b.x; tq.y += b.y; tq.z += b.z; tq.w += b.w;
        }
        size_t ps2 = (size_t)__cvta_generic_to_global(g_bnsum + lane * 4);
        asm volatile("red.global.add.v4.f32 [%0], {%1, %2, %3, %4};"
                     :: "l"(ps2), "f"(ts.x), "f"(ts.y), "f"(ts.z), "f"(ts.w)
                     : "memory");
        size_t pq = (size_t)__cvta_generic_to_global(g_bnsumsq + lane * 4);
        asm volatile("red.global.add.v4.f32 [%0], {%1, %2, %3, %4};"
                     :: "l"(pq), "f"(tq.x), "f"(tq.y), "f"(tq.z), "f"(tq.w)
                     : "memory");
    }
}

// ---------------- K4: BN finalize (1 block) ----------------
__global__ void k_bn_finalize(int n_nodes)
{
    int t = threadIdx.x;
    float inv_n = 1.f / (float)n_nodes;
    float mu  = g_bnsum[t] * inv_n;
    float var = g_bnsumsq[t] * inv_n - mu * mu;
    float sc  = gp_gamma[t] * rsqrtf(var + BN_EPS);
    g_scale[t] = sc;
    g_shift[t] = gp_beta[t] - mu * sc;
}

// ---------------- K5: apply BN in place ----------------
__global__ void __launch_bounds__(256) k_bn_apply(float* __restrict__ out, int n4)
{
    int i = blockIdx.x * 256 + threadIdx.x;   // float4 index
    if (i >= n4) return;
    float4 v = reinterpret_cast<float4*>(out)[i];
    int c = (i * 4) & (HC - 1);
    v.x = v.x * g_scale[c + 0] + g_shift[c + 0];
    v.y = v.y * g_scale[c + 1] + g_shift[c + 1];
    v.z = v.z * g_scale[c + 2] + g_shift[c + 2];
    v.w = v.w * g_scale[c + 3] + g_shift[c + 3];
    reinterpret_cast<float4*>(out)[i] = v;
}

// ---------------- launch ----------------
extern "C" void kernel_launch(void* const* d_in, const int* in_sizes, int n_in,
                              void* d_out, int out_size)
{
    // ---- identify inputs by element count (order-agnostic) ----
    const void*  ei_raw = nullptr;  int ei_sz = 0;
    const float* x  = nullptr;      int x_sz  = 0;
    const float* W  = nullptr;
    const float* vec[5] = {nullptr, nullptr, nullptr, nullptr, nullptr};
    int nv = 0;

    for (int i = 0; i < n_in; i++) {
        const int sz = in_sizes[i];
        if (sz == HC) {
            if (nv < 5) vec[nv++] = (const float*)d_in[i];
        } else if (sz == IN_DIM * HC) {
            W = (const float*)d_in[i];
        } else if (sz > 1000000) {
            if (x == nullptr) { x = (const float*)d_in[i]; x_sz = sz; }
            else if (sz > x_sz) {             // larger buffer is x
                ei_raw = (const void*)x; ei_sz = x_sz;
                x = (const float*)d_in[i]; x_sz = sz;
            } else { ei_raw = d_in[i]; ei_sz = sz; }
        }
    }

    const int n_nodes = x_sz / IN_DIM;
    const int n_edges = ei_sz / 2;
    float* out = (float*)d_out;

    const int nblk = (n_nodes + 255) / 256;

    // side stream + fork/join events (host objects, not device memory; created once)
    static cudaStream_t s_gemm = nullptr;
    static cudaEvent_t  ev_fork = nullptr, ev_join = nullptr;
    if (s_gemm == nullptr) {
        cudaStreamCreateWithFlags(&s_gemm, cudaStreamNonBlocking);
        cudaEventCreateWithFlags(&ev_fork, cudaEventDisableTiming);
        cudaEventCreateWithFlags(&ev_join, cudaEventDisableTiming);
    }

    const int smem = (IN_DIM * HC + IN_DIM * SX_PAD) * sizeof(float);  // ~74 KB
    cudaFuncSetAttribute(k_gemm, cudaFuncAttributeMaxDynamicSharedMemorySize, smem);

    k_detect_vec<<<1, 128>>>(vec[0], vec[1], vec[2], vec[3], vec[4]);
    k_detect_idx<<<1, 256>>>((const unsigned int*)ei_raw, n_edges, n_nodes);

    // ---- fork: GEMM on side stream, CSR build on main stream ----
    cudaEventRecord(ev_fork, 0);
    cudaStreamWaitEvent(s_gemm, ev_fork, 0);

    int gemm_blocks = (n_nodes + GEMM_ROWS - 1) / GEMM_ROWS;
    k_gemm<<<gemm_blocks, 128, smem, s_gemm>>>(x, W, n_nodes);
    cudaEventRecord(ev_join, s_gemm);

    k_zero<<<nblk, 256>>>(n_nodes);
    k_hist<<<(n_edges / 2 + 256) / 256, 256>>>(ei_raw, n_edges, n_nodes);
    k_scan_blk<<<nblk, 256>>>(n_nodes);
    k_scan_top<<<1, 256>>>(nblk);
    k_scan_add<<<nblk, 256>>>(n_nodes);
    k_fill<<<(n_edges / 2 + 256) / 256, 256>>>(n_edges);

    // ---- join: aggregation needs both ----
    cudaStreamWaitEvent(0, ev_join, 0);

    int agg_blocks = (n_nodes + 8 * NPW - 1) / (8 * NPW);
    k_agg<<<agg_blocks, 256>>>(out, n_nodes);

    k_bn_finalize<<<1, 128>>>(n_nodes);

    int n4 = n_nodes * HC / 4;
    k_bn_apply<<<(n4 + 255) / 256, 256>>>(out, n4);
}

// round 17
// speedup vs baseline: 1.0246x; 1.0246x over previous
#include <cuda_runtime.h>
#include <cuda_fp16.h>
#include <math.h>
#include <stdint.h>

#define MAX_NODES 50000
#define MAX_EDGES 1600000
#define HC        128        // HEADS * OUT_DIM
#define HEADS     4
#define IN_DIM    128
#define NEG_SLOPE 0.04821699482733621f
#define BN_EPS    1e-5f

// ---------------- scratch (static __device__ — no allocations allowed) ----------
__device__ __align__(16) __half g_hh[MAX_NODES * HC];   // fp16 message features
__device__ __align__(16) float g_as   [MAX_NODES * HEADS];
__device__ __align__(16) float g_ad   [MAX_NODES * HEADS];
__device__ __align__(16) int g_src [MAX_EDGES];
__device__ __align__(16) int g_dst [MAX_EDGES];
__device__ int   g_esrc [MAX_EDGES];      // CSR: src ids grouped by dst
__device__ int   g_deg  [MAX_NODES];
__device__ int   g_off  [MAX_NODES];
__device__ int   g_fill [MAX_NODES];
__device__ int   g_bsum [256];            // per-block scan sums (<=196 used)
__device__ int   g_boff [256];
__device__ int   g_idx_mode;              // 0=int32, 1=int64, 2=float32
__device__ __align__(16) float g_bnsum  [HC];
__device__ __align__(16) float g_bnsumsq[HC];
__device__ float g_scale  [HC];
__device__ float g_shift  [HC];

// Resolved parameter-vector pointers (runtime input-order detection)
__device__ const float* gp_a_src;
__device__ const float* gp_a_dst;
__device__ const float* gp_bias;
__device__ const float* gp_gamma;
__device__ const float* gp_beta;

// ---------------- helpers ----------------
__device__ __forceinline__ float warp_sum(float v) {
    v += __shfl_xor_sync(0xffffffffu, v, 16);
    v += __shfl_xor_sync(0xffffffffu, v, 8);
    v += __shfl_xor_sync(0xffffffffu, v, 4);
    v += __shfl_xor_sync(0xffffffffu, v, 2);
    v += __shfl_xor_sync(0xffffffffu, v, 1);
    return v;
}

__device__ __forceinline__ int warp_incl_scan(int v) {
    const int lane = threadIdx.x & 31;
    #pragma unroll
    for (int d = 1; d < 32; d <<= 1) {
        int t = __shfl_up_sync(0xffffffffu, v, d);
        if (lane >= d) v += t;
    }
    return v;
}

__device__ __forceinline__ float lrelu(float e) {
    return e >= 0.f ? e : NEG_SLOPE * e;
}

// unpack 4 fp16 channels (8 bytes) to float4
__device__ __forceinline__ float4 h4_to_f4(uint2 u) {
    __half2 a = *reinterpret_cast<__half2*>(&u.x);
    __half2 b = *reinterpret_cast<__half2*>(&u.y);
    return make_float4(__low2float(a), __high2float(a),
                       __low2float(b), __high2float(b));
}

// packed f32x2 FMA: acc = a * b + acc  (2 full-precision fp32 FMAs per instr)
__device__ __forceinline__ void ffma2(unsigned long long& acc,
                                      unsigned long long a, unsigned long long b) {
    asm("fma.rn.f32x2 %0, %1, %2, %0;" : "+l"(acc) : "l"(a), "l"(b));
}

// ---------------- K_detect_vec: resolve the five 128-float parameter vectors ----
__global__ void k_detect_vec(const float* p0, const float* p1, const float* p2,
                             const float* p3, const float* p4)
{
    const int t = threadIdx.x;
    int ones3 = __syncthreads_and(p3[t] == 1.0f);
    int ones4 = __syncthreads_and(p4[t] == 1.0f);
    if (t == 0) {
        if (ones3) {            // insertion order: a_src,a_dst,bias,gamma,beta
            gp_a_src = p0; gp_a_dst = p1; gp_bias = p2; gp_gamma = p3; gp_beta = p4;
        } else if (ones4) {     // alphabetical: a_dst,a_src,beta,bias,gamma
            gp_a_dst = p0; gp_a_src = p1; gp_beta = p2; gp_bias = p3; gp_gamma = p4;
        } else {
            gp_a_src = p0; gp_a_dst = p1; gp_bias = p2; gp_gamma = p3; gp_beta = p4;
        }
    }
}

// ---------------- K_detect_idx: classify edge_index dtype ----------------------
__global__ void k_detect_idx(const unsigned int* __restrict__ w, int n_edges, int n_nodes)
{
    __shared__ int s_hi_nz, s_int_ok, s_flt_ok;
    const int t = threadIdx.x;
    if (t == 0) { s_hi_nz = 0; s_int_ok = 0; s_flt_ok = 0; }
    __syncthreads();

    const int SAMPLES = 1024;
    const long long total_words = 2LL * n_edges;
    int hi_nz = 0, int_ok = 0, flt_ok = 0;
    for (int i = t; i < SAMPLES; i += blockDim.x) {
        long long pair = (long long)i * ((total_words / 2) / SAMPLES);
        unsigned int lo = w[2 * pair];
        unsigned int hi = w[2 * pair + 1];
        if (hi != 0u) hi_nz++;
        int vi = (int)lo;
        if (vi >= 0 && vi < n_nodes) int_ok++;
        float vf = __uint_as_float(lo);
        if (vf >= 0.f && vf < (float)n_nodes && vf == floorf(vf)) flt_ok++;
    }
    atomicAdd(&s_hi_nz, hi_nz);
    atomicAdd(&s_int_ok, int_ok);
    atomicAdd(&s_flt_ok, flt_ok);
    __syncthreads();
    if (t == 0) {
        if (s_hi_nz == 0)               g_idx_mode = 1;
        else if (s_int_ok >= s_flt_ok)  g_idx_mode = 0;
        else                            g_idx_mode = 2;
    }
}

// ---------------- K0: zero degree histogram + BN accumulators -------------------
__global__ void __launch_bounds__(256) k_zero(int n_nodes) {
    int i = blockIdx.x * 256 + threadIdx.x;
    if (i < n_nodes) g_deg[i] = 0;
    if (i < HC) { g_bnsum[i] = 0.f; g_bnsumsq[i] = 0.f; }
}

// ---------------- K_hist: decode indices (clamped) + degree histogram ----------
__global__ void __launch_bounds__(256) k_hist(const void* __restrict__ raw,
                                              int n_edges, int n_nodes)
{
    const int i  = blockIdx.x * 256 + threadIdx.x;   // pair index
    const int e0 = 2 * i;
    if (e0 >= n_edges) return;
    const int  mode = g_idx_mode;
    const bool full = (e0 + 1 < n_edges);

    long long vs0, vs1 = 0, vd0, vd1 = 0;
    if (mode == 1) {
        const longlong2* sp = (const longlong2*)raw;
        const long long* dbase = (const long long*)raw + n_edges;
        longlong2 s = sp[i];
        vs0 = s.x; vs1 = s.y;
        if (((size_t)n_edges & 1) == 0 && full) {
            longlong2 d = ((const longlong2*)dbase)[i];
            vd0 = d.x; vd1 = d.y;
        } else {
            vd0 = dbase[e0];
            vd1 = full ? dbase[e0 + 1] : 0;
        }
    } else if (mode == 0) {
        const int2* sp = (const int2*)raw;
        const int* dbase = (const int*)raw + n_edges;
        int2 s = sp[i];
        vs0 = s.x; vs1 = s.y;
        if (((size_t)n_edges & 1) == 0 && full) {
            int2 d = ((const int2*)dbase)[i];
            vd0 = d.x; vd1 = d.y;
        } else {
            vd0 = dbase[e0];
            vd1 = full ? dbase[e0 + 1] : 0;
        }
    } else {
        const float2* sp = (const float2*)raw;
        const float* dbase = (const float*)raw + n_edges;
        float2 s = sp[i];
        vs0 = (long long)s.x; vs1 = (long long)s.y;
        vd0 = (long long)dbase[e0];
        vd1 = full ? (long long)dbase[e0 + 1] : 0;
    }
    if (vs0 < 0 || vs0 >= n_nodes) vs0 = 0;   // defensive clamp
    if (vs1 < 0 || vs1 >= n_nodes) vs1 = 0;
    if (vd0 < 0 || vd0 >= n_nodes) vd0 = 0;
    if (vd1 < 0 || vd1 >= n_nodes) vd1 = 0;

    if (full) {
        *(int2*)(g_src + e0) = make_int2((int)vs0, (int)vs1);
        *(int2*)(g_dst + e0) = make_int2((int)vd0, (int)vd1);
        atomicAdd(&g_deg[(int)vd0], 1);
        atomicAdd(&g_deg[(int)vd1], 1);
    } else {
        g_src[e0] = (int)vs0;
        g_dst[e0] = (int)vd0;
        atomicAdd(&g_deg[(int)vd0], 1);
    }
}

// ---------------- scan (3 kernels, warp-shuffle based) --------------------------
__global__ void __launch_bounds__(256) k_scan_blk(int n_nodes)
{
    __shared__ int wsum[8];
    const int i    = blockIdx.x * 256 + threadIdx.x;
    const int lane = threadIdx.x & 31;
    const int wid  = threadIdx.x >> 5;

    int v = (i < n_nodes) ? g_deg[i] : 0;
    int s = warp_incl_scan(v);
    if (lane == 31) wsum[wid] = s;
    __syncthreads();
    if (wid == 0) {
        int w  = (lane < 8) ? wsum[lane] : 0;
        int ws = warp_incl_scan(w);
        if (lane < 8) wsum[lane] = ws - w;            // exclusive warp offsets
        if (lane == 7) g_bsum[blockIdx.x] = ws;       // block total
    }
    __syncthreads();
    if (i < n_nodes) g_off[i] = s - v + wsum[wid];
}

__global__ void __launch_bounds__(256) k_scan_top(int nblk)
{
    __shared__ int wsum[8];
    const int t    = threadIdx.x;
    const int lane = t & 31;
    const int wid  = t >> 5;
    int v = (t < nblk) ? g_bsum[t] : 0;
    int s = warp_incl_scan(v);
    if (lane == 31) wsum[wid] = s;
    __syncthreads();
    if (wid == 0) {
        int w  = (lane < 8) ? wsum[lane] : 0;
        int ws = warp_incl_scan(w);
        if (lane < 8) wsum[lane] = ws - w;
    }
    __syncthreads();
    if (t < nblk) g_boff[t] = s - v + wsum[wid];
}

__global__ void __launch_bounds__(256) k_scan_add(int n_nodes)
{
    const int i = blockIdx.x * 256 + threadIdx.x;
    if (i >= n_nodes) return;
    int o = g_off[i] + g_boff[blockIdx.x];
    g_off[i]  = o;
    g_fill[i] = o;
}

// ---------------- K_fill: bucket edge srcs by dst (2 edges/thread) --------------
__global__ void __launch_bounds__(256) k_fill(int n_edges)
{
    const int i  = blockIdx.x * 256 + threadIdx.x;
    const int e0 = 2 * i;
    if (e0 >= n_edges) return;
    if (e0 + 1 < n_edges) {
        int2 s = *(const int2*)(g_src + e0);
        int2 d = *(const int2*)(g_dst + e0);
        int p0 = atomicAdd(&g_fill[d.x], 1);
        int p1 = atomicAdd(&g_fill[d.y], 1);
        g_esrc[p0] = s.x;
        g_esrc[p1] = s.y;
    } else {
        int s = g_src[e0];
        int d = g_dst[e0];
        int p = atomicAdd(&g_fill[d], 1);
        g_esrc[p] = s;
    }
}

// ---------------- K1: h = x @ W via packed f32x2 FMA (exact fp32) ---------------
#define GEMM_ROWS 16
#define SX_PAD    20                       // 16 rows padded to 20 (16B-aligned rows)
__global__ void __launch_bounds__(128) k_gemm(
    const float* __restrict__ x, const float* __restrict__ W, int n_nodes)
{
    extern __shared__ float sm[];
    float* sW  = sm;                        // [128][128]
    float* sxT = sm + IN_DIM * HC;          // [128][SX_PAD]  (k-major, rows r)

    const int t    = threadIdx.x;
    const int row0 = blockIdx.x * GEMM_ROWS;

    for (int i = t; i < IN_DIM * HC; i += 128) sW[i] = W[i];
    #pragma unroll
    for (int r = 0; r < GEMM_ROWS; r++) {
        int node = row0 + r;
        sxT[t * SX_PAD + r] = (node < n_nodes) ? x[(size_t)node * IN_DIM + t] : 0.f;
    }
    __syncthreads();

    // 8 packed accumulators; acc2[j] holds rows (2j, 2j+1)
    unsigned long long acc2[8];
    #pragma unroll
    for (int j = 0; j < 8; j++) acc2[j] = 0ull;

    #pragma unroll 2
    for (int k = 0; k < IN_DIM; k++) {
        unsigned int wb = __float_as_uint(sW[k * HC + t]);
        unsigned long long w2;
        asm("mov.b64 %0, {%1, %1};" : "=l"(w2) : "r"(wb));
        const ulonglong2* xr = (const ulonglong2*)(sxT + k * SX_PAD);  // 16B-aligned
        ulonglong2 p0 = xr[0], p1 = xr[1], p2 = xr[2], p3 = xr[3];
        ffma2(acc2[0], p0.x, w2);  ffma2(acc2[1], p0.y, w2);
        ffma2(acc2[2], p1.x, w2);  ffma2(acc2[3], p1.y, w2);
        ffma2(acc2[4], p2.x, w2);  ffma2(acc2[5], p2.y, w2);
        ffma2(acc2[6], p3.x, w2);  ffma2(acc2[7], p3.y, w2);
    }

    float accf[GEMM_ROWS];
    #pragma unroll
    for (int j = 0; j < 8; j++) {
        float2 fr = *reinterpret_cast<float2*>(&acc2[j]);
        accf[2 * j]     = fr.x;
        accf[2 * j + 1] = fr.y;
    }

    const float asv  = gp_a_src[t];
    const float adv  = gp_a_dst[t];
    const int   head = t >> 5;
    const int   lane = t & 31;

    #pragma unroll
    for (int r = 0; r < GEMM_ROWS; r++) {
        int node = row0 + r;
        if (node >= n_nodes) break;
        float hv = accf[r];
        g_hh[(size_t)node * HC + t] = __float2half(hv);
        float s = warp_sum(hv * asv);     // fp32 attention logits (exact path)
        float d = warp_sum(hv * adv);
        if (lane == 0) {
            g_as[node * HEADS + head] = s;
            g_ad[node * HEADS + head] = d;
        }
    }
}

// ---------------- K_agg: gather-aggregate + full epilogue -----------------------
// NPW=2 (measured optimum). BN partials reduced across the block's 8 warps in
// smem; one red.v4 pair per block.
#define NPW 2   // nodes per warp
__global__ void __launch_bounds__(256) k_agg(float* __restrict__ out, int n_nodes)
{
    __shared__ float sbn[2][8][HC];          // [sum|sq][warp][channel]

    const int wid  = threadIdx.x >> 5;
    const int warp = blockIdx.x * 8 + wid;
    const int lane = threadIdx.x & 31;
    const int head = lane >> 3;

    const float4 bias4 = *((const float4*)gp_bias + lane);

    float4 lsum = make_float4(0.f, 0.f, 0.f, 0.f);
    float4 lsq  = make_float4(0.f, 0.f, 0.f, 0.f);

    const int node0 = warp * NPW;
    const int node1 = (node0 + NPW < n_nodes) ? node0 + NPW : n_nodes;

    for (int d = node0; d < node1; d++) {
        float adl = 0.f, dsum = 0.f, pself = 0.f;
        if (lane < HEADS) {
            adl   = g_ad[d * HEADS + lane];
            pself = __expf(lrelu(g_as[d * HEADS + lane] + adl));
            dsum  = pself;
        }
        float ps = __shfl_sync(0xffffffffu, pself, head);

        uint2 ud = *((const uint2*)(g_hh + (size_t)d * HC) + lane);
        float4 hd = h4_to_f4(ud);
        float4 acc;
        acc.x = hd.x * ps; acc.y = hd.y * ps; acc.z = hd.z * ps; acc.w = hd.w * ps;

        const int start = g_off[d];
        const int end   = start + g_deg[d];
        int k = start;

        for (; k + 8 <= end; k += 8) {
            int s[8];
            #pragma unroll
            for (int j = 0; j < 8; j++) s[j] = g_esrc[k + j];

            float p[8];
            #pragma unroll
            for (int j = 0; j < 8; j++) p[j] = 0.f;
            if (lane < HEADS) {
                #pragma unroll
                for (int j = 0; j < 8; j++) {
                    p[j] = __expf(lrelu(g_as[s[j] * HEADS + lane] + adl));
                    dsum += p[j];
                }
            }
            uint2 u[8];
            #pragma unroll
            for (int j = 0; j < 8; j++)
                u[j] = *((const uint2*)(g_hh + (size_t)s[j] * HC) + lane);

            #pragma unroll
            for (int j = 0; j < 8; j++) {
                float q = __shfl_sync(0xffffffffu, p[j], head);
                float4 h = h4_to_f4(u[j]);
                acc.x += h.x * q; acc.y += h.y * q; acc.z += h.z * q; acc.w += h.w * q;
            }
        }
        for (; k < end; k++) {
            int s0 = g_esrc[k];
            float p0 = 0.f;
            if (lane < HEADS) {
                p0 = __expf(lrelu(g_as[s0 * HEADS + lane] + adl));
                dsum += p0;
            }
            uint2 u0 = *((const uint2*)(g_hh + (size_t)s0 * HC) + lane);
            float q0 = __shfl_sync(0xffffffffu, p0, head);
            float4 h0 = h4_to_f4(u0);
            acc.x += h0.x * q0; acc.y += h0.y * q0; acc.z += h0.z * q0; acc.w += h0.w * q0;
        }

        float den = __shfl_sync(0xffffffffu, dsum, head);
        float inv = 1.0f / den;

        float4 v;
        v.x = acc.x * inv + bias4.x;
        v.y = acc.y * inv + bias4.y;
        v.z = acc.z * inv + bias4.z;
        v.w = acc.w * inv + bias4.w;

        *((float4*)(out + (size_t)d * HC) + lane) = v;

        lsum.x += v.x; lsum.y += v.y; lsum.z += v.z; lsum.w += v.w;
        lsq.x += v.x * v.x; lsq.y += v.y * v.y; lsq.z += v.z * v.z; lsq.w += v.w * v.w;
    }

    // block-level BN reduction: per-warp partials -> smem -> warp 0 -> one red/block
    *((float4*)&sbn[0][wid][lane * 4]) = lsum;
    *((float4*)&sbn[1][wid][lane * 4]) = lsq;
    __syncthreads();
    if (wid == 0) {
        float4 ts = make_float4(0.f, 0.f, 0.f, 0.f);
        float4 tq = make_float4(0.f, 0.f, 0.f, 0.f);
        #pragma unroll
        for (int w = 0; w < 8; w++) {
            float4 a = *((const float4*)&sbn[0][w][lane * 4]);
            float4 b = *((const float4*)&sbn[1][w][lane * 4]);
            ts.x += a.x; ts.y += a.y; ts.z += a.z; ts.w += a.w;
            tq.x += b.x; tq.y += b.y; tq.z += b.z; tq.w += b.w;
        }
        size_t ps2 = (size_t)__cvta_generic_to_global(g_bnsum + lane * 4);
        asm volatile("red.global.add.v4.f32 [%0], {%1, %2, %3, %4};"
                     :: "l"(ps2), "f"(ts.x), "f"(ts.y), "f"(ts.z), "f"(ts.w)
                     : "memory");
        size_t pq = (size_t)__cvta_generic_to_global(g_bnsumsq + lane * 4);
        asm volatile("red.global.add.v4.f32 [%0], {%1, %2, %3, %4};"
                     :: "l"(pq), "f"(tq.x), "f"(tq.y), "f"(tq.z), "f"(tq.w)
                     : "memory");
    }
}

// ---------------- K4: BN finalize (1 block) ----------------
__global__ void k_bn_finalize(int n_nodes)
{
    int t = threadIdx.x;
    float inv_n = 1.f / (float)n_nodes;
    float mu  = g_bnsum[t] * inv_n;
    float var = g_bnsumsq[t] * inv_n - mu * mu;
    float sc  = gp_gamma[t] * rsqrtf(var + BN_EPS);
    g_scale[t] = sc;
    g_shift[t] = gp_beta[t] - mu * sc;
}

// ---------------- K5: apply BN in place ----------------
__global__ void __launch_bounds__(256) k_bn_apply(float* __restrict__ out, int n4)
{
    int i = blockIdx.x * 256 + threadIdx.x;   // float4 index
    if (i >= n4) return;
    float4 v = reinterpret_cast<float4*>(out)[i];
    int c = (i * 4) & (HC - 1);
    v.x = v.x * g_scale[c + 0] + g_shift[c + 0];
    v.y = v.y * g_scale[c + 1] + g_shift[c + 1];
    v.z = v.z * g_scale[c + 2] + g_shift[c + 2];
    v.w = v.w * g_scale[c + 3] + g_shift[c + 3];
    reinterpret_cast<float4*>(out)[i] = v;
}

// ---------------- launch ----------------
extern "C" void kernel_launch(void* const* d_in, const int* in_sizes, int n_in,
                              void* d_out, int out_size)
{
    // ---- identify inputs by element count (order-agnostic) ----
    const void*  ei_raw = nullptr;  int ei_sz = 0;
    const float* x  = nullptr;      int x_sz  = 0;
    const float* W  = nullptr;
    const float* vec[5] = {nullptr, nullptr, nullptr, nullptr, nullptr};
    int nv = 0;

    for (int i = 0; i < n_in; i++) {
        const int sz = in_sizes[i];
        if (sz == HC) {
            if (nv < 5) vec[nv++] = (const float*)d_in[i];
        } else if (sz == IN_DIM * HC) {
            W = (const float*)d_in[i];
        } else if (sz > 1000000) {
            if (x == nullptr) { x = (const float*)d_in[i]; x_sz = sz; }
            else if (sz > x_sz) {             // larger buffer is x
                ei_raw = (const void*)x; ei_sz = x_sz;
                x = (const float*)d_in[i]; x_sz = sz;
            } else { ei_raw = d_in[i]; ei_sz = sz; }
        }
    }

    const int n_nodes = x_sz / IN_DIM;
    const int n_edges = ei_sz / 2;
    float* out = (float*)d_out;

    const int nblk = (n_nodes + 255) / 256;

    // side stream + fork/join events (host objects, not device memory; created once)
    static cudaStream_t s_gemm = nullptr;
    static cudaEvent_t  ev_fork = nullptr, ev_join = nullptr;
    if (s_gemm == nullptr) {
        cudaStreamCreateWithFlags(&s_gemm, cudaStreamNonBlocking);
        cudaEventCreateWithFlags(&ev_fork, cudaEventDisableTiming);
        cudaEventCreateWithFlags(&ev_join, cudaEventDisableTiming);
    }

    const int smem = (IN_DIM * HC + IN_DIM * SX_PAD) * sizeof(float);  // ~74 KB
    cudaFuncSetAttribute(k_gemm, cudaFuncAttributeMaxDynamicSharedMemorySize, smem);

    // ---- fork immediately: detect_vec + GEMM on side stream; CSR on main -------
    cudaEventRecord(ev_fork, 0);
    cudaStreamWaitEvent(s_gemm, ev_fork, 0);

    k_detect_vec<<<1, 128, 0, s_gemm>>>(vec[0], vec[1], vec[2], vec[3], vec[4]);
    int gemm_blocks = (n_nodes + GEMM_ROWS - 1) / GEMM_ROWS;
    k_gemm<<<gemm_blocks, 128, smem, s_gemm>>>(x, W, n_nodes);
    cudaEventRecord(ev_join, s_gemm);

    k_detect_idx<<<1, 256>>>((const unsigned int*)ei_raw, n_edges, n_nodes);
    k_zero<<<nblk, 256>>>(n_nodes);
    k_hist<<<(n_edges / 2 + 256) / 256, 256>>>(ei_raw, n_edges, n_nodes);
    k_scan_blk<<<nblk, 256>>>(n_nodes);
    k_scan_top<<<1, 256>>>(nblk);
    k_scan_add<<<nblk, 256>>>(n_nodes);
    k_fill<<<(n_edges / 2 + 256) / 256, 256>>>(n_edges);

    // ---- join: aggregation needs both ----
    cudaStreamWaitEvent(0, ev_join, 0);

    int agg_blocks = (n_nodes + 8 * NPW - 1) / (8 * NPW);
    k_agg<<<agg_blocks, 256>>>(out, n_nodes);

    k_bn_finalize<<<1, 128>>>(n_nodes);

    int n4 = n_nodes * HC / 4;
    k_bn_apply<<<(n4 + 255) / 256, 256>>>(out, n4);
}